// round 1
// baseline (speedup 1.0000x reference)
#include <cuda_runtime.h>
#include <cstdint>

#define N_NODES 50000
#define N_EDGES 800000
#define EDGE_DIM 16
#define EMB 128
#define HID 256

typedef unsigned long long u64;

// ------------------------- scratch (static device arrays; no allocs) -------
__device__ float g_agg_n[(size_t)N_NODES * EMB];     // sum of node_feats[src] per dst, then full agg
__device__ float g_agg_e[(size_t)N_NODES * EDGE_DIM];// sum of raw edge feats per dst
__device__ float g_deg[N_NODES];                     // in-degree (float)
__device__ float g_c1[(size_t)N_NODES * HID];        // relu(agg@W1+b1)
__device__ float g_h[(size_t)N_NODES * EMB];         // pre-BN output
__device__ float g_sum[EMB];
__device__ float g_sumsq[EMB];
__device__ float g_scale[EMB];
__device__ float g_shift[EMB];

// ------------------------- zero scratch ------------------------------------
__global__ void zero_kernel() {
  int i = blockIdx.x * blockDim.x + threadIdx.x;
  int stride = gridDim.x * blockDim.x;
  const int T1 = N_NODES * EMB;
  const int T2 = T1 + N_NODES * EDGE_DIM;
  const int T3 = T2 + N_NODES;
  const int T4 = T3 + 2 * EMB;
  for (; i < T4; i += stride) {
    if (i < T1) g_agg_n[i] = 0.f;
    else if (i < T2) g_agg_e[i - T1] = 0.f;
    else if (i < T3) g_deg[i - T2] = 0.f;
    else if (i < T3 + EMB) g_sum[i - T3] = 0.f;
    else g_sumsq[i - T3 - EMB] = 0.f;
  }
}

// ------------------------- vector reduction to global ----------------------
__device__ __forceinline__ void red4(float* p, float4 v) {
  asm volatile("red.global.add.v4.f32 [%0], {%1,%2,%3,%4};"
               :: "l"(p), "f"(v.x), "f"(v.y), "f"(v.z), "f"(v.w) : "memory");
}

// One warp per edge: gather full 128-f node row (1 LDG.128/lane) and one
// red.v4 per lane; lanes 0..3 also scatter the 16 raw edge features.
__global__ void edge_kernel(const float* __restrict__ nf, const float* __restrict__ ef,
                            const int* __restrict__ src, const int* __restrict__ dst) {
  int e = (blockIdx.x * blockDim.x + threadIdx.x) >> 5;
  int lane = threadIdx.x & 31;
  if (e >= N_EDGES) return;
  int s = src[e], d = dst[e];
  float4 v = reinterpret_cast<const float4*>(nf)[s * (EMB / 4) + lane];
  red4(&g_agg_n[d * EMB + lane * 4], v);
  if (lane < EDGE_DIM / 4) {
    float4 ev = reinterpret_cast<const float4*>(ef)[e * (EDGE_DIM / 4) + lane];
    red4(&g_agg_e[d * EDGE_DIM + lane * 4], ev);
  }
  if (lane == 0) atomicAdd(&g_deg[d], 1.0f);
}

// agg = agg_n + agg_e @ W_edge + deg * b_edge   (in place on g_agg_n)
__global__ void combine_kernel(const float* __restrict__ W_edge,
                               const float* __restrict__ b_edge) {
  __shared__ float se[EDGE_DIM];
  __shared__ float sdeg;
  int n = blockIdx.x;
  int j = threadIdx.x;
  if (j < EDGE_DIM) se[j] = g_agg_e[n * EDGE_DIM + j];
  if (j == 0) sdeg = g_deg[n];
  __syncthreads();
  float acc = g_agg_n[n * EMB + j] + sdeg * b_edge[j];
#pragma unroll
  for (int i = 0; i < EDGE_DIM; i++)
    acc = fmaf(se[i], W_edge[i * EMB + j], acc);
  g_agg_n[n * EMB + j] = acc;
}

// ------------------------- packed fp32x2 FMA GEMM ---------------------------
__device__ __forceinline__ void ffma2(u64& d, u64 a, u64 b) {
  asm("fma.rn.f32x2 %0, %1, %2, %0;" : "+l"(d) : "l"(a), "l"(b));
}

// BM=BN=128, BK=16, 256 threads, 8x8 per thread (as 8x4 f32x2 pairs).
// A values duplicated in smem (u64 = {a,a}) so the inner loop is pure
// LDS.64 + FFMA2 with zero packing MOVs; both operand layouts are swizzled
// (slot = (idx & mask)*16 + idx>>shift) so LDS.64 is bank-conflict-free.
template<bool FIRST>
__global__ __launch_bounds__(256, 2)
void gemm_kernel(const float* __restrict__ B, const float* __restrict__ bias) {
  constexpr int K = FIRST ? EMB : HID;
  constexpr int N = FIRST ? HID : EMB;
  constexpr int M = N_NODES;
  const float* __restrict__ A = FIRST ? g_agg_n : g_c1;
  float* __restrict__ C = FIRST ? g_c1 : g_h;

  __shared__ u64 As64[16][128];  // duplicated A, swizzled: slot(m) = (m&7)*16 + m>>3
  __shared__ u64 Bs64[16][64];   // B col-pairs, swizzled: slot(p) = (p&3)*16 + p>>2
  float* As32 = reinterpret_cast<float*>(&As64[0][0]);
  float* Bs32 = reinterpret_cast<float*>(&Bs64[0][0]);

  int tid = threadIdx.x;
  int tx = tid & 15, ty = tid >> 4;
  int bm = blockIdx.y * 128, bn = blockIdx.x * 128;

  u64 acc[8][4];
#pragma unroll
  for (int i = 0; i < 8; i++)
#pragma unroll
    for (int j = 0; j < 4; j++) acc[i][j] = 0ull;

  for (int k0 = 0; k0 < K; k0 += 16) {
#pragma unroll
    for (int l = 0; l < 2; l++) {
      int idx = tid + l * 256;
      int row = idx >> 2;
      int kc = (idx & 3) << 2;
      int gr = bm + row;
      float4 v = make_float4(0.f, 0.f, 0.f, 0.f);
      if (gr < M) v = *reinterpret_cast<const float4*>(&A[(size_t)gr * K + k0 + kc]);
      int slot = ((row & 7) << 4) | (row >> 3);
      As32[(kc + 0) * 256 + slot * 2] = v.x; As32[(kc + 0) * 256 + slot * 2 + 1] = v.x;
      As32[(kc + 1) * 256 + slot * 2] = v.y; As32[(kc + 1) * 256 + slot * 2 + 1] = v.y;
      As32[(kc + 2) * 256 + slot * 2] = v.z; As32[(kc + 2) * 256 + slot * 2 + 1] = v.z;
      As32[(kc + 3) * 256 + slot * 2] = v.w; As32[(kc + 3) * 256 + slot * 2 + 1] = v.w;
    }
#pragma unroll
    for (int l = 0; l < 2; l++) {
      int idx = tid + l * 256;
      int kr = idx >> 5;
      int col = (idx & 31) << 2;
      float4 v = *reinterpret_cast<const float4*>(&B[(size_t)(k0 + kr) * N + bn + col]);
      int p0 = col >> 1;
      int s0 = ((p0 & 3) << 4) | (p0 >> 2);
      int p1 = p0 + 1;
      int s1 = ((p1 & 3) << 4) | (p1 >> 2);
      Bs32[kr * 128 + s0 * 2] = v.x; Bs32[kr * 128 + s0 * 2 + 1] = v.y;
      Bs32[kr * 128 + s1 * 2] = v.z; Bs32[kr * 128 + s1 * 2 + 1] = v.w;
    }
    __syncthreads();
#pragma unroll
    for (int k = 0; k < 16; k++) {
      u64 a[8], b[4];
#pragma unroll
      for (int j = 0; j < 4; j++) b[j] = Bs64[k][(j << 4) | tx];
#pragma unroll
      for (int i = 0; i < 8; i++) a[i] = As64[k][(i << 4) | ty];
#pragma unroll
      for (int i = 0; i < 8; i++)
#pragma unroll
        for (int j = 0; j < 4; j++) ffma2(acc[i][j], a[i], b[j]);
    }
    __syncthreads();
  }

  float bb[8];
#pragma unroll
  for (int j = 0; j < 8; j++) bb[j] = bias[bn + tx * 8 + j];
  float csum[8], csq[8];
#pragma unroll
  for (int j = 0; j < 8; j++) { csum[j] = 0.f; csq[j] = 0.f; }

#pragma unroll
  for (int i = 0; i < 8; i++) {
    int gr = bm + ty * 8 + i;
    if (gr < M) {
      float o[8];
#pragma unroll
      for (int j = 0; j < 4; j++) {
        float2 v = *reinterpret_cast<float2*>(&acc[i][j]);
        o[2 * j] = v.x + bb[2 * j];
        o[2 * j + 1] = v.y + bb[2 * j + 1];
      }
#pragma unroll
      for (int j = 0; j < 8; j++) {
        if (FIRST) o[j] = fmaxf(o[j], 0.f);
        else { csum[j] += o[j]; csq[j] += o[j] * o[j]; }
      }
      float4 o0 = make_float4(o[0], o[1], o[2], o[3]);
      float4 o1 = make_float4(o[4], o[5], o[6], o[7]);
      *reinterpret_cast<float4*>(&C[(size_t)gr * N + bn + tx * 8]) = o0;
      *reinterpret_cast<float4*>(&C[(size_t)gr * N + bn + tx * 8 + 4]) = o1;
    }
  }

  if (!FIRST) {
    // fused BN stats: smem reduce (reuse As64) then 2 atomics per column/block
    float* red = As32;
    __syncthreads();
#pragma unroll
    for (int j = 0; j < 8; j++) red[ty * 128 + tx * 8 + j] = csum[j];
    __syncthreads();
    if (tid < 128) {
      float s = 0.f;
#pragma unroll
      for (int r = 0; r < 16; r++) s += red[r * 128 + tid];
      atomicAdd(&g_sum[tid], s);
    }
    __syncthreads();
#pragma unroll
    for (int j = 0; j < 8; j++) red[ty * 128 + tx * 8 + j] = csq[j];
    __syncthreads();
    if (tid < 128) {
      float s = 0.f;
#pragma unroll
      for (int r = 0; r < 16; r++) s += red[r * 128 + tid];
      atomicAdd(&g_sumsq[tid], s);
    }
  }
}

__global__ void bn_finalize(const float* __restrict__ gamma, const float* __restrict__ beta) {
  int n = threadIdx.x;
  const float invM = 1.0f / (float)N_NODES;
  float mean = g_sum[n] * invM;
  float var = g_sumsq[n] * invM - mean * mean;
  float sc = gamma[n] * rsqrtf(var + 1e-5f);
  g_scale[n] = sc;
  g_shift[n] = beta[n] - mean * sc;
}

__global__ void bn_apply(float* __restrict__ out) {
  int i = blockIdx.x * blockDim.x + threadIdx.x;
  const int total4 = N_NODES * EMB / 4;
  if (i >= total4) return;
  int c = (i & 31) << 2;  // column base within the 128-wide row
  float4 h = reinterpret_cast<const float4*>(g_h)[i];
  float4 o;
  o.x = h.x * g_scale[c + 0] + g_shift[c + 0];
  o.y = h.y * g_scale[c + 1] + g_shift[c + 1];
  o.z = h.z * g_scale[c + 2] + g_shift[c + 2];
  o.w = h.w * g_scale[c + 3] + g_shift[c + 3];
  reinterpret_cast<float4*>(out)[i] = o;
}

// ------------------------- launch -------------------------------------------
extern "C" void kernel_launch(void* const* d_in, const int* in_sizes, int n_in,
                              void* d_out, int out_size) {
  const float* node_feats = (const float*)d_in[0];
  const float* edge_feats = (const float*)d_in[1];
  const float* W_edge     = (const float*)d_in[2];
  const float* b_edge     = (const float*)d_in[3];
  const float* W1         = (const float*)d_in[4];
  const float* b1         = (const float*)d_in[5];
  const float* W2         = (const float*)d_in[6];
  const float* b2         = (const float*)d_in[7];
  const float* bn_gamma   = (const float*)d_in[8];
  const float* bn_beta    = (const float*)d_in[9];
  const int*   src        = (const int*)d_in[10];
  const int*   dst        = (const int*)d_in[11];
  float* out = (float*)d_out;

  zero_kernel<<<2048, 256>>>();
  edge_kernel<<<(N_EDGES + 7) / 8, 256>>>(node_feats, edge_feats, src, dst);
  combine_kernel<<<N_NODES, EMB>>>(W_edge, b_edge);
  dim3 g1(HID / 128, (N_NODES + 127) / 128);
  gemm_kernel<true><<<g1, 256>>>(W1, b1);
  dim3 g2(EMB / 128, (N_NODES + 127) / 128);
  gemm_kernel<false><<<g2, 256>>>(W2, b2);
  bn_finalize<<<1, EMB>>>(bn_gamma, bn_beta);
  bn_apply<<<(N_NODES * EMB / 4 + 255) / 256, 256>>>(out);
}

// round 3
// speedup vs baseline: 1.0061x; 1.0061x over previous
#include <cuda_runtime.h>
#include <mma.h>
#include <cstdint>

using namespace nvcuda;

#define N_NODES 50000
#define N_EDGES 800000
#define EDGE_DIM 16
#define EMB 128
#define HID 256

// ------------------------- scratch (static device arrays; no allocs) -------
__device__ float g_agg_n[(size_t)N_NODES * EMB];
__device__ float g_agg_e[(size_t)N_NODES * EDGE_DIM];
__device__ float g_deg[N_NODES];
__device__ float g_c1[(size_t)N_NODES * HID];
__device__ float g_h[(size_t)N_NODES * EMB];
__device__ float g_sum[EMB];
__device__ float g_sumsq[EMB];
__device__ float g_scale[EMB];
__device__ float g_shift[EMB];

// ------------------------- zero scratch ------------------------------------
__global__ void zero_kernel() {
  int i = blockIdx.x * blockDim.x + threadIdx.x;
  int stride = gridDim.x * blockDim.x;
  const int T1 = N_NODES * EMB;
  const int T2 = T1 + N_NODES * EDGE_DIM;
  const int T3 = T2 + N_NODES;
  const int T4 = T3 + 2 * EMB;
  for (; i < T4; i += stride) {
    if (i < T1) g_agg_n[i] = 0.f;
    else if (i < T2) g_agg_e[i - T1] = 0.f;
    else if (i < T3) g_deg[i - T2] = 0.f;
    else if (i < T3 + EMB) g_sum[i - T3] = 0.f;
    else g_sumsq[i - T3 - EMB] = 0.f;
  }
}

// ------------------------- edge scatter -------------------------------------
__device__ __forceinline__ void red4(float* p, float4 v) {
  asm volatile("red.global.add.v4.f32 [%0], {%1,%2,%3,%4};"
               :: "l"(p), "f"(v.x), "f"(v.y), "f"(v.z), "f"(v.w) : "memory");
}

__global__ void edge_kernel(const float* __restrict__ nf, const float* __restrict__ ef,
                            const int* __restrict__ src, const int* __restrict__ dst) {
  int e = (blockIdx.x * blockDim.x + threadIdx.x) >> 5;
  int lane = threadIdx.x & 31;
  if (e >= N_EDGES) return;
  int s = src[e], d = dst[e];
  float4 v = reinterpret_cast<const float4*>(nf)[s * (EMB / 4) + lane];
  red4(&g_agg_n[d * EMB + lane * 4], v);
  if (lane < EDGE_DIM / 4) {
    float4 ev = reinterpret_cast<const float4*>(ef)[e * (EDGE_DIM / 4) + lane];
    red4(&g_agg_e[d * EDGE_DIM + lane * 4], ev);
  }
  if (lane == 0) atomicAdd(&g_deg[d], 1.0f);
}

// agg = agg_n + agg_e @ W_edge + deg * b_edge   (in place on g_agg_n)
__global__ void combine_kernel(const float* __restrict__ W_edge,
                               const float* __restrict__ b_edge) {
  __shared__ float se[EDGE_DIM];
  __shared__ float sdeg;
  int n = blockIdx.x;
  int j = threadIdx.x;
  if (j < EDGE_DIM) se[j] = g_agg_e[n * EDGE_DIM + j];
  if (j == 0) sdeg = g_deg[n];
  __syncthreads();
  float acc = g_agg_n[n * EMB + j] + sdeg * b_edge[j];
#pragma unroll
  for (int i = 0; i < EDGE_DIM; i++)
    acc = fmaf(se[i], W_edge[i * EMB + j], acc);
  g_agg_n[n * EMB + j] = acc;
}

// ------------------------- wmma tf32 GEMM -----------------------------------
// C[M, N_] = A[M, K_] @ W[K_, N_] + bias, optional ReLU.
// tf32 3-term split (AhiBhi + AloBhi + AhiBlo) -> ~fp32 accuracy.
// CTA tile 128x128, BK=32 single-buffered; 8 warps of 32x64 (2m x 4n frags).
#define AS_STRIDE 40
#define BS_STRIDE 136
#define AS_FLOATS (128 * AS_STRIDE)     // 5120
#define BS_FLOATS (32 * BS_STRIDE)      // 4352
#define SB_FLOATS (16 * BS_STRIDE)      // 2176
#define GEMM_SMEM_FLOATS (2 * AS_FLOATS + 2 * BS_FLOATS + SB_FLOATS)  // 21120
#define GEMM_SMEM_BYTES (GEMM_SMEM_FLOATS * 4)                        // 84480

__device__ __forceinline__ void split2(float x, float& hi, float& lo) {
  hi = wmma::__float_to_tf32(x);
  lo = wmma::__float_to_tf32(x - hi);
}

template <int N_, int K_, bool FIRST>
__global__ __launch_bounds__(256, 2)
void wmma_gemm(const float* __restrict__ Aglob_unused, const float* __restrict__ W,
               const float* __restrict__ bias) {
  constexpr int M = N_NODES;
  const float* __restrict__ A = FIRST ? g_agg_n : g_c1;
  float* __restrict__ C       = FIRST ? g_c1 : g_h;

  extern __shared__ float sm[];
  float* As_hi = sm;
  float* As_lo = sm + AS_FLOATS;
  float* Bs_hi = sm + 2 * AS_FLOATS;
  float* Bs_lo = sm + 2 * AS_FLOATS + BS_FLOATS;
  float* sb    = sm + 2 * AS_FLOATS + 2 * BS_FLOATS;

  int tid = threadIdx.x;
  int wid = tid >> 5;
  int wm = wid & 3;          // 0..3 : 32-row strip
  int wn = wid >> 2;         // 0..1 : 64-col strip
  int bm = blockIdx.y * 128;
  int bn = blockIdx.x * 128;

  // bias tile, replicated over 16 rows so it can be loaded as an acc fragment
  for (int i = tid; i < 16 * 128; i += 256) {
    int r = i >> 7, c = i & 127;
    sb[r * BS_STRIDE + c] = bias[bn + c];
  }

  wmma::fragment<wmma::accumulator, 16, 16, 8, float> acc[2][4];
#pragma unroll
  for (int mt = 0; mt < 2; mt++)
#pragma unroll
    for (int nt = 0; nt < 4; nt++) wmma::fill_fragment(acc[mt][nt], 0.f);

  for (int k0 = 0; k0 < K_; k0 += 32) {
    __syncthreads();
    // ---- A chunk: 128 rows x 32 cols ----
#pragma unroll
    for (int l = 0; l < 4; l++) {
      int idx = tid + l * 256;           // 0..1023 float4 slots
      int row = idx >> 3;
      int c4 = (idx & 7) << 2;
      int gr = bm + row;
      float4 v = make_float4(0.f, 0.f, 0.f, 0.f);
      if (gr < M) v = *reinterpret_cast<const float4*>(&A[(size_t)gr * K_ + k0 + c4]);
      float4 hv, lv;
      split2(v.x, hv.x, lv.x); split2(v.y, hv.y, lv.y);
      split2(v.z, hv.z, lv.z); split2(v.w, hv.w, lv.w);
      *reinterpret_cast<float4*>(&As_hi[row * AS_STRIDE + c4]) = hv;
      *reinterpret_cast<float4*>(&As_lo[row * AS_STRIDE + c4]) = lv;
    }
    // ---- B chunk: 32 rows x 128 cols (W is [K_, N_] row-major) ----
#pragma unroll
    for (int l = 0; l < 4; l++) {
      int idx = tid + l * 256;
      int row = idx >> 5;
      int c4 = (idx & 31) << 2;
      float4 v = *reinterpret_cast<const float4*>(&W[(size_t)(k0 + row) * N_ + bn + c4]);
      float4 hv, lv;
      split2(v.x, hv.x, lv.x); split2(v.y, hv.y, lv.y);
      split2(v.z, hv.z, lv.z); split2(v.w, hv.w, lv.w);
      *reinterpret_cast<float4*>(&Bs_hi[row * BS_STRIDE + c4]) = hv;
      *reinterpret_cast<float4*>(&Bs_lo[row * BS_STRIDE + c4]) = lv;
    }
    __syncthreads();

#pragma unroll
    for (int k8 = 0; k8 < 4; k8++) {
      wmma::fragment<wmma::matrix_a, 16, 16, 8, wmma::precision::tf32, wmma::row_major> ah[2], al[2];
#pragma unroll
      for (int mt = 0; mt < 2; mt++) {
        const float* ap = &As_hi[(wm * 32 + mt * 16) * AS_STRIDE + k8 * 8];
        wmma::load_matrix_sync(ah[mt], ap, AS_STRIDE);
        wmma::load_matrix_sync(al[mt], ap + AS_FLOATS, AS_STRIDE);
      }
#pragma unroll
      for (int nt = 0; nt < 4; nt++) {
        wmma::fragment<wmma::matrix_b, 16, 16, 8, wmma::precision::tf32, wmma::row_major> bh, bl;
        const float* bp = &Bs_hi[(k8 * 8) * BS_STRIDE + wn * 64 + nt * 16];
        wmma::load_matrix_sync(bh, bp, BS_STRIDE);
        wmma::load_matrix_sync(bl, bp + BS_FLOATS, BS_STRIDE);
#pragma unroll
        for (int mt = 0; mt < 2; mt++) {
          wmma::mma_sync(acc[mt][nt], ah[mt], bh, acc[mt][nt]);
          wmma::mma_sync(acc[mt][nt], al[mt], bh, acc[mt][nt]);
          wmma::mma_sync(acc[mt][nt], ah[mt], bl, acc[mt][nt]);
        }
      }
    }
  }

  // ---- epilogue: bias (+relu) then direct global store ----
#pragma unroll
  for (int nt = 0; nt < 4; nt++) {
    wmma::fragment<wmma::accumulator, 16, 16, 8, float> bf;
    wmma::load_matrix_sync(bf, &sb[wn * 64 + nt * 16], BS_STRIDE, wmma::mem_row_major);
#pragma unroll
    for (int mt = 0; mt < 2; mt++) {
#pragma unroll
      for (int e = 0; e < bf.num_elements; e++) {
        float v = acc[mt][nt].x[e] + bf.x[e];
        if (FIRST) v = fmaxf(v, 0.f);
        acc[mt][nt].x[e] = v;
      }
      int row0 = bm + wm * 32 + mt * 16;
      if (row0 < M)  // M % 16 == 0, so row0 < M means the full 16-row tile is valid
        wmma::store_matrix_sync(&C[(size_t)row0 * N_ + bn + wn * 64 + nt * 16],
                                acc[mt][nt], N_, wmma::mem_row_major);
    }
  }
}

// ------------------------- BN stats over g_h --------------------------------
__global__ void bn_stats() {
  __shared__ float4 ssum[8][32];
  __shared__ float4 ssq[8][32];
  int tid = threadIdx.x;
  int r0 = tid >> 5;
  int cq = tid & 31;
  int base = blockIdx.x * 128;
  float4 s = make_float4(0.f, 0.f, 0.f, 0.f);
  float4 q = make_float4(0.f, 0.f, 0.f, 0.f);
#pragma unroll
  for (int step = 0; step < 16; step++) {
    int row = base + r0 + step * 8;
    if (row < N_NODES) {
      float4 h = reinterpret_cast<const float4*>(g_h)[row * 32 + cq];
      s.x += h.x; s.y += h.y; s.z += h.z; s.w += h.w;
      q.x += h.x * h.x; q.y += h.y * h.y; q.z += h.z * h.z; q.w += h.w * h.w;
    }
  }
  ssum[r0][cq] = s;
  ssq[r0][cq] = q;
  __syncthreads();
  if (tid < 32) {
    float4 ts = ssum[0][tid], tq = ssq[0][tid];
#pragma unroll
    for (int r = 1; r < 8; r++) {
      float4 a = ssum[r][tid], b2 = ssq[r][tid];
      ts.x += a.x; ts.y += a.y; ts.z += a.z; ts.w += a.w;
      tq.x += b2.x; tq.y += b2.y; tq.z += b2.z; tq.w += b2.w;
    }
    atomicAdd(&g_sum[tid * 4 + 0], ts.x); atomicAdd(&g_sum[tid * 4 + 1], ts.y);
    atomicAdd(&g_sum[tid * 4 + 2], ts.z); atomicAdd(&g_sum[tid * 4 + 3], ts.w);
    atomicAdd(&g_sumsq[tid * 4 + 0], tq.x); atomicAdd(&g_sumsq[tid * 4 + 1], tq.y);
    atomicAdd(&g_sumsq[tid * 4 + 2], tq.z); atomicAdd(&g_sumsq[tid * 4 + 3], tq.w);
  }
}

__global__ void bn_finalize(const float* __restrict__ gamma, const float* __restrict__ beta) {
  int n = threadIdx.x;
  const float invM = 1.0f / (float)N_NODES;
  float mean = g_sum[n] * invM;
  float var = g_sumsq[n] * invM - mean * mean;
  float sc = gamma[n] * rsqrtf(var + 1e-5f);
  g_scale[n] = sc;
  g_shift[n] = beta[n] - mean * sc;
}

__global__ void bn_apply(float* __restrict__ out) {
  int i = blockIdx.x * blockDim.x + threadIdx.x;
  const int total4 = N_NODES * EMB / 4;
  if (i >= total4) return;
  int c = (i & 31) << 2;
  float4 h = reinterpret_cast<const float4*>(g_h)[i];
  float4 o;
  o.x = h.x * g_scale[c + 0] + g_shift[c + 0];
  o.y = h.y * g_scale[c + 1] + g_shift[c + 1];
  o.z = h.z * g_scale[c + 2] + g_shift[c + 2];
  o.w = h.w * g_scale[c + 3] + g_shift[c + 3];
  reinterpret_cast<float4*>(out)[i] = o;
}

// ------------------------- launch -------------------------------------------
extern "C" void kernel_launch(void* const* d_in, const int* in_sizes, int n_in,
                              void* d_out, int out_size) {
  const float* node_feats = (const float*)d_in[0];
  const float* edge_feats = (const float*)d_in[1];
  const float* W_edge     = (const float*)d_in[2];
  const float* b_edge     = (const float*)d_in[3];
  const float* W1         = (const float*)d_in[4];
  const float* b1         = (const float*)d_in[5];
  const float* W2         = (const float*)d_in[6];
  const float* b2         = (const float*)d_in[7];
  const float* bn_gamma   = (const float*)d_in[8];
  const float* bn_beta    = (const float*)d_in[9];
  const int*   src        = (const int*)d_in[10];
  const int*   dst        = (const int*)d_in[11];
  float* out = (float*)d_out;

  cudaFuncSetAttribute(wmma_gemm<HID, EMB, true>,
                       cudaFuncAttributeMaxDynamicSharedMemorySize, GEMM_SMEM_BYTES);
  cudaFuncSetAttribute(wmma_gemm<EMB, HID, false>,
                       cudaFuncAttributeMaxDynamicSharedMemorySize, GEMM_SMEM_BYTES);

  const int MTILES = (N_NODES + 127) / 128;  // 391

  zero_kernel<<<2048, 256>>>();
  edge_kernel<<<(N_EDGES + 7) / 8, 256>>>(node_feats, edge_feats, src, dst);
  combine_kernel<<<N_NODES, EMB>>>(W_edge, b_edge);
  dim3 g1(HID / 128, MTILES);
  wmma_gemm<HID, EMB, true><<<g1, 256, GEMM_SMEM_BYTES>>>(nullptr, W1, b1);
  dim3 g2(EMB / 128, MTILES);
  wmma_gemm<EMB, HID, false><<<g2, 256, GEMM_SMEM_BYTES>>>(nullptr, W2, b2);
  bn_stats<<<MTILES, 256>>>();
  bn_finalize<<<1, EMB>>>(bn_gamma, bn_beta);
  bn_apply<<<(N_NODES * EMB / 4 + 255) / 256, 256>>>(out);
}